// round 1
// baseline (speedup 1.0000x reference)
#include <cuda_runtime.h>
#include <cuda_bf16.h>

// Shapes (fixed by the problem):
//  B=8, N=1024, F=320, H=5, D=64, packed QK cols = 640
//  scale = D^-0.5 = 0.125, TEMP=0.3, NEG_FILL=-1e-7, keep top N/6+1 = 171 per row

#define BATCH 8
#define SEQ   1024
#define FDIM  320
#define PACK  640

// ---------------- scratch (no allocation allowed -> device globals) ----------
__device__ __align__(16) float g_qk[BATCH * SEQ * PACK];   // packed qk projection
__device__ __align__(16) float g_Q [BATCH * SEQ * FDIM];
__device__ __align__(16) float g_K [BATCH * SEQ * FDIM];
__device__ __align__(16) float g_hW[BATCH * SEQ * FDIM];   // h @ weight
__device__ __align__(16) float g_at[BATCH * SEQ * SEQ];    // attention logits -> probs (in place)

// ---------------- tiled SGEMM --------------------------------------------
// C[m,n] = alpha * sum_k A[m,k]*B(k,n)  (+ bias[n])
//  A row-major, lda.  TRANSB=false: B(k,n)=B[k*ldb+n]; TRANSB=true: B(k,n)=B[n*ldb+k]
// Tiles: BM=128, BN=64, BK=16; 256 threads; 8x4 per-thread microtile.
// All problem dims divide tiles exactly -> no bounds checks.

#define BM 128
#define BN 64
#define BK 16
#define AS_LD 132   // 128 + 4 pad -> A-store smem conflicts <= 2-way, keeps 16B alignment
#define BS_LD 68    // 64 + 4 pad

template<bool TRANSB>
__global__ __launch_bounds__(256) void sgemm_kernel(
    const float* __restrict__ A, int lda, long long strideA,
    const float* __restrict__ B, int ldb, long long strideB,
    float* __restrict__ C, int ldc, long long strideC,
    const float* __restrict__ bias,
    int K, float alpha)
{
    __shared__ __align__(16) float As[BK * AS_LD];
    __shared__ __align__(16) float Bs[BK * BS_LD];

    const int bz = blockIdx.z;
    A += (long long)bz * strideA + (long long)blockIdx.y * BM * lda;
    if (TRANSB) B += (long long)bz * strideB + (long long)blockIdx.x * BN * ldb;
    else        B += (long long)bz * strideB + (long long)blockIdx.x * BN;
    C += (long long)bz * strideC + (long long)blockIdx.y * BM * ldc
                                 + (long long)blockIdx.x * BN;

    const int tid = threadIdx.x;
    const int tx  = tid & 15;   // 0..15 -> N
    const int ty  = tid >> 4;   // 0..15 -> M

    float acc[8][4];
    #pragma unroll
    for (int i = 0; i < 8; i++)
        #pragma unroll
        for (int j = 0; j < 4; j++) acc[i][j] = 0.f;

    for (int k0 = 0; k0 < K; k0 += BK) {
        // ---- load A tile (BM x BK), store transposed into As[k][m] ----
        {
            int q = tid;
            #pragma unroll
            for (int it = 0; it < 2; it++, q += 256) {
                int m  = q >> 2;            // 0..127
                int k4 = (q & 3) << 2;      // 0,4,8,12
                float4 v = *(const float4*)(A + (long long)m * lda + k0 + k4);
                As[(k4 + 0) * AS_LD + m] = v.x;
                As[(k4 + 1) * AS_LD + m] = v.y;
                As[(k4 + 2) * AS_LD + m] = v.z;
                As[(k4 + 3) * AS_LD + m] = v.w;
            }
        }
        // ---- load B tile (BK x BN) into Bs[k][n] ----
        if (!TRANSB) {
            int k  = tid >> 4;              // 0..15
            int n4 = (tid & 15) << 2;       // 0..60
            float4 v = *(const float4*)(B + (long long)(k0 + k) * ldb + n4);
            *(float4*)(Bs + k * BS_LD + n4) = v;
        } else {
            int n  = tid >> 2;              // 0..63
            int k4 = (tid & 3) << 2;        // 0,4,8,12
            float4 v = *(const float4*)(B + (long long)n * ldb + k0 + k4);
            Bs[(k4 + 0) * BS_LD + n] = v.x;
            Bs[(k4 + 1) * BS_LD + n] = v.y;
            Bs[(k4 + 2) * BS_LD + n] = v.z;
            Bs[(k4 + 3) * BS_LD + n] = v.w;
        }
        __syncthreads();

        // ---- microkernel ----
        #pragma unroll
        for (int kk = 0; kk < BK; kk++) {
            float4 a0 = *(const float4*)(As + kk * AS_LD + ty * 8);
            float4 a1 = *(const float4*)(As + kk * AS_LD + ty * 8 + 4);
            float4 b0 = *(const float4*)(Bs + kk * BS_LD + tx * 4);
            float av[8] = {a0.x, a0.y, a0.z, a0.w, a1.x, a1.y, a1.z, a1.w};
            float bv[4] = {b0.x, b0.y, b0.z, b0.w};
            #pragma unroll
            for (int i = 0; i < 8; i++)
                #pragma unroll
                for (int j = 0; j < 4; j++)
                    acc[i][j] = fmaf(av[i], bv[j], acc[i][j]);
        }
        __syncthreads();
    }

    // ---- epilogue ----
    float4 bv = make_float4(0.f, 0.f, 0.f, 0.f);
    if (bias) bv = *(const float4*)(bias + (long long)blockIdx.x * BN + tx * 4);
    #pragma unroll
    for (int i = 0; i < 8; i++) {
        int m = ty * 8 + i;
        float4 o;
        o.x = acc[i][0] * alpha + bv.x;
        o.y = acc[i][1] * alpha + bv.y;
        o.z = acc[i][2] * alpha + bv.z;
        o.w = acc[i][3] * alpha + bv.w;
        *(float4*)(C + (long long)m * ldc + tx * 4) = o;
    }
}

// ---------------- deinterleave packed qk -> Q (even cols), K (odd cols) -----
__global__ void deinterleave_kernel(const float* __restrict__ qk,
                                    float* __restrict__ Q,
                                    float* __restrict__ Kk)
{
    int i = blockIdx.x * blockDim.x + threadIdx.x;      // over B*N*F
    if (i < BATCH * SEQ * FDIM) {
        int row = i / FDIM, f = i - row * FDIM;
        float2 v = *(const float2*)(qk + (long long)row * PACK + 2 * f);
        Q[i]  = v.x;
        Kk[i] = v.y;
    }
}

// ---------------- per-row top-k threshold + masked softmax (in place) -------
// One block per row. Exact 171st-largest via in-smem bitonic sort (1024 = 2^10).
__global__ __launch_bounds__(256) void mask_softmax_kernel(float* __restrict__ at)
{
    __shared__ float xbuf[SEQ];
    __shared__ float sbuf[SEQ];
    __shared__ float red[8];

    const int tid = threadIdx.x;
    float* row = at + (long long)blockIdx.x * SEQ;

    #pragma unroll
    for (int c = 0; c < 4; c++) {
        float v = row[tid + 256 * c];
        xbuf[tid + 256 * c] = v;
        sbuf[tid + 256 * c] = v;
    }
    __syncthreads();

    // bitonic sort ascending
    for (int k = 2; k <= SEQ; k <<= 1) {
        for (int j = k >> 1; j > 0; j >>= 1) {
            #pragma unroll
            for (int c = 0; c < 4; c++) {
                int i   = tid + 256 * c;
                int ixj = i ^ j;
                if (ixj > i) {
                    float a = sbuf[i], b = sbuf[ixj];
                    bool up = ((i & k) == 0);
                    if ((a > b) == up) { sbuf[i] = b; sbuf[ixj] = a; }
                }
            }
            __syncthreads();
        }
    }

    const float thr = sbuf[SEQ - (SEQ / 6 + 1)];   // 171st largest

    // adj + row max
    float adj[4];
    float lmax = -3.402823466e38f;
    #pragma unroll
    for (int c = 0; c < 4; c++) {
        float v = xbuf[tid + 256 * c];
        v = (v < thr) ? -1e-7f : v;
        adj[c] = v;
        lmax = fmaxf(lmax, v);
    }
    #pragma unroll
    for (int o = 16; o > 0; o >>= 1)
        lmax = fmaxf(lmax, __shfl_xor_sync(0xFFFFFFFFu, lmax, o));
    if ((tid & 31) == 0) red[tid >> 5] = lmax;
    __syncthreads();
    if (tid < 32) {
        float m = (tid < 8) ? red[tid] : -3.402823466e38f;
        #pragma unroll
        for (int o = 4; o > 0; o >>= 1)
            m = fmaxf(m, __shfl_xor_sync(0xFFFFFFFFu, m, o));
        if (tid == 0) red[0] = m;
    }
    __syncthreads();
    const float m = red[0];
    __syncthreads();

    // exp + row sum
    const float inv_t = 1.0f / 0.3f;
    float e[4];
    float lsum = 0.f;
    #pragma unroll
    for (int c = 0; c < 4; c++) {
        e[c] = __expf((adj[c] - m) * inv_t);
        lsum += e[c];
    }
    #pragma unroll
    for (int o = 16; o > 0; o >>= 1)
        lsum += __shfl_xor_sync(0xFFFFFFFFu, lsum, o);
    if ((tid & 31) == 0) red[tid >> 5] = lsum;
    __syncthreads();
    if (tid < 32) {
        float s = (tid < 8) ? red[tid] : 0.f;
        #pragma unroll
        for (int o = 4; o > 0; o >>= 1)
            s += __shfl_xor_sync(0xFFFFFFFFu, s, o);
        if (tid == 0) red[0] = s;
    }
    __syncthreads();
    const float inv_sum = 1.0f / red[0];

    #pragma unroll
    for (int c = 0; c < 4; c++)
        row[tid + 256 * c] = e[c] * inv_sum;
}

// ---------------- launch --------------------------------------------------
extern "C" void kernel_launch(void* const* d_in, const int* in_sizes, int n_in,
                              void* d_out, int out_size)
{
    const float* h      = (const float*)d_in[0];   // [8,1024,320]
    const float* Wqk    = (const float*)d_in[1];   // [320,640]
    const float* bqk    = (const float*)d_in[2];   // [640]
    const float* weight = (const float*)d_in[3];   // [320,320]
    const float* bias   = (const float*)d_in[4];   // [320]
    float* out = (float*)d_out;                    // [8,1024,320]

    float *qk, *Q, *K, *hW, *at;
    cudaGetSymbolAddress((void**)&qk, g_qk);
    cudaGetSymbolAddress((void**)&Q,  g_Q);
    cudaGetSymbolAddress((void**)&K,  g_K);
    cudaGetSymbolAddress((void**)&hW, g_hW);
    cudaGetSymbolAddress((void**)&at, g_at);

    const long long NF = (long long)SEQ * FDIM;    // 327680
    const long long NN = (long long)SEQ * SEQ;     // 1048576

    // 1) packed QK projection: [8192,320] @ [320,640] + bqk
    sgemm_kernel<false><<<dim3(PACK / BN, (BATCH * SEQ) / BM, 1), 256>>>(
        h, FDIM, 0, Wqk, PACK, 0, qk, PACK, 0, bqk, FDIM, 1.0f);

    // 2) split even/odd columns -> Q, K
    deinterleave_kernel<<<(BATCH * SEQ * FDIM + 255) / 256, 256>>>(qk, Q, K);

    // 3) hW = h @ weight  (bias folded into final GEMM epilogue)
    sgemm_kernel<false><<<dim3(FDIM / BN, (BATCH * SEQ) / BM, 1), 256>>>(
        h, FDIM, 0, weight, FDIM, 0, hW, FDIM, 0, nullptr, FDIM, 1.0f);

    // 4) at[b] = 0.125 * Q[b] @ K[b]^T    (per-batch 1024x1024x320, NT)
    sgemm_kernel<true><<<dim3(SEQ / BN, SEQ / BM, BATCH), 256>>>(
        Q, FDIM, NF, K, FDIM, NF, at, SEQ, NN, nullptr, FDIM, 0.125f);

    // 5) per-row top-171 threshold mask + softmax(x/0.3), in place
    mask_softmax_kernel<<<BATCH * SEQ, 256>>>(at);

    // 6) out[b] = attn[b] @ hW[b] + bias  (per-batch 1024x320x1024, NN)
    sgemm_kernel<false><<<dim3(FDIM / BN, SEQ / BM, BATCH), 256>>>(
        at, SEQ, NN, hW, FDIM, NF, out, FDIM, NF, bias, SEQ, 1.0f);
}